// round 5
// baseline (speedup 1.0000x reference)
#include <cuda_runtime.h>

#define S_LEN 4096
#define HID   512
#define NHEAD 8
#define HDIM  64

// Scratch (device globals — allocation-free per harness rules)
__device__ float g_q[S_LEN * HID];
__device__ float g_k[S_LEN * HID];
__device__ float g_v[S_LEN * HID];
__device__ float g_att[S_LEN * HID];

// ---------------------------------------------------------------------------
// C[M,N] = A[M,K] * B[N,K]^T   (both operands K-major, matches einsum bsh,oh->bso)
// 64x64 tile, BK=32, 128 threads, 8x4 register micro-tile per thread.
// Thread owns columns n = nb + tx + 16*j (strided to keep Bs LDS conflict-free).
// ---------------------------------------------------------------------------
__global__ __launch_bounds__(128) void gemm_nt(const float* __restrict__ A,
                                               const float* __restrict__ B,
                                               float* __restrict__ C,
                                               int M, int N, int K) {
    __shared__ float As[64][36];
    __shared__ float Bs[64][36];
    const int tid = threadIdx.x;
    const int mb = blockIdx.y * 64;
    const int nb = blockIdx.x * 64;
    const int tx = tid & 15;       // 16 columns groups
    const int ty = tid >> 4;       // 8 row groups

    float acc[8][4];
#pragma unroll
    for (int i = 0; i < 8; i++)
#pragma unroll
        for (int j = 0; j < 4; j++) acc[i][j] = 0.f;

    for (int kb = 0; kb < K; kb += 32) {
#pragma unroll
        for (int i = 0; i < 4; i++) {
            int fid = tid + i * 128;         // 0..511 float4 slots (64 rows x 8)
            int r = fid >> 3, c4 = fid & 7;
            float4 av = *reinterpret_cast<const float4*>(&A[(mb + r) * K + kb + c4 * 4]);
            *reinterpret_cast<float4*>(&As[r][c4 * 4]) = av;
            float4 bv = *reinterpret_cast<const float4*>(&B[(nb + r) * K + kb + c4 * 4]);
            *reinterpret_cast<float4*>(&Bs[r][c4 * 4]) = bv;
        }
        __syncthreads();
#pragma unroll
        for (int k4 = 0; k4 < 8; k4++) {
            float4 b4[4];
#pragma unroll
            for (int j = 0; j < 4; j++)
                b4[j] = *reinterpret_cast<const float4*>(&Bs[tx + 16 * j][k4 * 4]);
#pragma unroll
            for (int i = 0; i < 8; i++) {
                float4 a4 = *reinterpret_cast<const float4*>(&As[ty * 8 + i][k4 * 4]);
#pragma unroll
                for (int j = 0; j < 4; j++) {
                    acc[i][j] += a4.x * b4[j].x + a4.y * b4[j].y +
                                 a4.z * b4[j].z + a4.w * b4[j].w;
                }
            }
        }
        __syncthreads();
    }
#pragma unroll
    for (int i = 0; i < 8; i++) {
        int row = mb + ty * 8 + i;
#pragma unroll
        for (int j = 0; j < 4; j++)
            C[row * N + nb + tx + 16 * j] = acc[i][j];
    }
}

// ---------------------------------------------------------------------------
// RoPE on Q and K, positions s >= num_registers, rotation index p = s - nreg.
// cos/sin rows are concat([freqs,freqs]) so cos[p][j] == cos[p][j+32].
// ---------------------------------------------------------------------------
__global__ void rope_kernel(float* __restrict__ q, float* __restrict__ k,
                            const float* __restrict__ cosb,
                            const float* __restrict__ sinb,
                            const int* __restrict__ nregp) {
    const int nreg = *nregp;
    int idx = blockIdx.x * blockDim.x + threadIdx.x;   // over S*8*32 pairs
    if (idx >= S_LEN * NHEAD * 32) return;
    int j = idx & 31;
    int h = (idx >> 5) & 7;
    int s = idx >> 8;
    if (s < nreg) return;
    int p = s - nreg;
    float c  = cosb[p * HDIM + j];
    float sn = sinb[p * HDIM + j];
    int base = s * HID + h * HDIM + j;
    float q1 = q[base], q2 = q[base + 32];
    q[base]      = q1 * c - q2 * sn;
    q[base + 32] = q2 * c + q1 * sn;
    float k1 = k[base], k2 = k[base + 32];
    k[base]      = k1 * c - k2 * sn;
    k[base + 32] = k2 * c + k1 * sn;
}

// ---------------------------------------------------------------------------
// Flash attention, causal. 64-query x 64-key tiles, 256 threads (8 warps).
// Each warp owns 8 query rows; each lane holds dims {lane, lane+32} of O.
// Row-stride 68 floats in smem: float4 LDS across 32 consecutive rows hits
// 8 distinct bank starts per 8-lane phase -> conflict-free.
// ---------------------------------------------------------------------------
#define AT_STRIDE 68
#define AT_SMEM   (4 * 64 * AT_STRIDE * 4)

__global__ __launch_bounds__(256, 3) void attn_kernel(const float* __restrict__ Q,
                                                      const float* __restrict__ Kb,
                                                      const float* __restrict__ Vb,
                                                      float* __restrict__ O) {
    extern __shared__ float sm[];
    float* Qs = sm;                       // [64][68]
    float* Ks = sm + 64 * AT_STRIDE;      // [64][68]
    float* Vt = sm + 2 * 64 * AT_STRIDE;  // [64][68]  (V transposed: Vt[dd][k])
    float* Ps = sm + 3 * 64 * AT_STRIDE;  // [64][68]

    const int tid  = threadIdx.x;
    const int lane = tid & 31;
    const int warp = tid >> 5;
    const int head = blockIdx.x & 7;
    const int qt   = 63 - (blockIdx.x >> 3);   // descending work for LPT packing
    const int qbase = qt * 64;
    const int hoff  = head * HDIM;
    const float scale = 0.125f;                // 1/sqrt(64)

    // Load Q tile once, pre-scaled
#pragma unroll
    for (int i = 0; i < 4; i++) {
        int fid = tid + i * 256;               // 0..1023 float4 slots
        int r = fid >> 4, c4 = fid & 15;
        float4 v = *reinterpret_cast<const float4*>(&Q[(qbase + r) * HID + hoff + c4 * 4]);
        v.x *= scale; v.y *= scale; v.z *= scale; v.w *= scale;
        *reinterpret_cast<float4*>(&Qs[r * AT_STRIDE + c4 * 4]) = v;
    }

    float m[8], l[8], o0[8], o1[8];
#pragma unroll
    for (int r = 0; r < 8; r++) { m[r] = -1e30f; l[r] = 0.f; o0[r] = 0.f; o1[r] = 0.f; }

    const int rbase = warp * 8;
    const int ntiles = qt + 1;

    for (int t = 0; t < ntiles; t++) {
        const int kb0 = t * 64;
        __syncthreads();   // previous iteration's Vt/Ks reads done
        // Load K tile
#pragma unroll
        for (int i = 0; i < 4; i++) {
            int fid = tid + i * 256;
            int r = fid >> 4, c4 = fid & 15;
            *reinterpret_cast<float4*>(&Ks[r * AT_STRIDE + c4 * 4]) =
                *reinterpret_cast<const float4*>(&Kb[(kb0 + r) * HID + hoff + c4 * 4]);
        }
        // Load V transposed (coalesced gmem read, ~4-way STS conflict tolerated)
#pragma unroll
        for (int i = 0; i < 16; i++) {
            int idx = tid + i * 256;           // 0..4095
            int k = idx >> 6, dd = idx & 63;
            Vt[dd * AT_STRIDE + k] = Vb[(kb0 + k) * HID + hoff + dd];
        }
        __syncthreads();

        // S = Q * K^T (each lane: columns {lane, lane+32}, rows rbase..rbase+7)
        float s0[8], s1[8];
#pragma unroll
        for (int r = 0; r < 8; r++) { s0[r] = 0.f; s1[r] = 0.f; }
#pragma unroll
        for (int d4 = 0; d4 < 16; d4++) {
            float4 kA = *reinterpret_cast<const float4*>(&Ks[lane * AT_STRIDE + d4 * 4]);
            float4 kB = *reinterpret_cast<const float4*>(&Ks[(lane + 32) * AT_STRIDE + d4 * 4]);
#pragma unroll
            for (int r = 0; r < 8; r++) {
                float4 q = *reinterpret_cast<const float4*>(&Qs[(rbase + r) * AT_STRIDE + d4 * 4]);
                s0[r] += q.x * kA.x + q.y * kA.y + q.z * kA.z + q.w * kA.w;
                s1[r] += q.x * kB.x + q.y * kB.y + q.z * kB.z + q.w * kB.w;
            }
        }

        const bool diag = (t == qt);   // only the diagonal tile needs masking
#pragma unroll
        for (int r = 0; r < 8; r++) {
            int qg = qbase + rbase + r;
            if (diag) {
                if (kb0 + lane      > qg) s0[r] = -1e30f;
                if (kb0 + lane + 32 > qg) s1[r] = -1e30f;
            }
            float tm = fmaxf(s0[r], s1[r]);
#pragma unroll
            for (int ofs = 16; ofs; ofs >>= 1)
                tm = fmaxf(tm, __shfl_xor_sync(0xffffffffu, tm, ofs));
            float mnew  = fmaxf(m[r], tm);
            float alpha = __expf(m[r] - mnew);
            float p0 = __expf(s0[r] - mnew);
            float p1 = __expf(s1[r] - mnew);
            float ps = p0 + p1;
#pragma unroll
            for (int ofs = 16; ofs; ofs >>= 1)
                ps += __shfl_xor_sync(0xffffffffu, ps, ofs);
            l[r] = l[r] * alpha + ps;
            m[r] = mnew;
            o0[r] *= alpha;
            o1[r] *= alpha;
            Ps[(rbase + r) * AT_STRIDE + lane]      = p0;
            Ps[(rbase + r) * AT_STRIDE + lane + 32] = p1;
        }
        __syncwarp();   // P rows are warp-private; warp-level visibility suffices

        // O += P * V   (Vt[dd][k] so vA.x..w = V[4k4..][lane])
#pragma unroll
        for (int k4 = 0; k4 < 16; k4++) {
            float4 vA = *reinterpret_cast<const float4*>(&Vt[lane * AT_STRIDE + k4 * 4]);
            float4 vB = *reinterpret_cast<const float4*>(&Vt[(lane + 32) * AT_STRIDE + k4 * 4]);
#pragma unroll
            for (int r = 0; r < 8; r++) {
                float4 p = *reinterpret_cast<const float4*>(&Ps[(rbase + r) * AT_STRIDE + k4 * 4]);
                o0[r] += p.x * vA.x + p.y * vA.y + p.z * vA.z + p.w * vA.w;
                o1[r] += p.x * vB.x + p.y * vB.y + p.z * vB.z + p.w * vB.w;
            }
        }
    }

#pragma unroll
    for (int r = 0; r < 8; r++) {
        int qg = qbase + rbase + r;
        float inv = 1.0f / l[r];
        O[qg * HID + hoff + lane]      = o0[r] * inv;
        O[qg * HID + hoff + lane + 32] = o1[r] * inv;
    }
}

// ---------------------------------------------------------------------------
// Host launcher (graph-capturable: kernel launches only)
// Inputs: hidden, Wq, Wk, Wv, Wo, cos, sin, num_registers
// ---------------------------------------------------------------------------
extern "C" void kernel_launch(void* const* d_in, const int* in_sizes, int n_in,
                              void* d_out, int out_size) {
    const float* hs   = (const float*)d_in[0];
    const float* Wq   = (const float*)d_in[1];
    const float* Wk   = (const float*)d_in[2];
    const float* Wv   = (const float*)d_in[3];
    const float* Wo   = (const float*)d_in[4];
    const float* cosb = (const float*)d_in[5];
    const float* sinb = (const float*)d_in[6];
    const int*   nreg = (const int*)d_in[7];
    float* out = (float*)d_out;

    float *qp, *kp, *vp, *ap;
    cudaGetSymbolAddress((void**)&qp, g_q);
    cudaGetSymbolAddress((void**)&kp, g_k);
    cudaGetSymbolAddress((void**)&vp, g_v);
    cudaGetSymbolAddress((void**)&ap, g_att);

    dim3 ggrid(HID / 64, S_LEN / 64);   // (8, 64)
    gemm_nt<<<ggrid, 128>>>(hs, Wq, qp, S_LEN, HID, HID);
    gemm_nt<<<ggrid, 128>>>(hs, Wk, kp, S_LEN, HID, HID);
    gemm_nt<<<ggrid, 128>>>(hs, Wv, vp, S_LEN, HID, HID);

    rope_kernel<<<(S_LEN * NHEAD * 32 + 255) / 256, 256>>>(qp, kp, cosb, sinb, nreg);

    cudaFuncSetAttribute(attn_kernel, cudaFuncAttributeMaxDynamicSharedMemorySize, AT_SMEM);
    attn_kernel<<<512, 256, AT_SMEM>>>(qp, kp, vp, ap);

    gemm_nt<<<ggrid, 128>>>(ap, Wo, out, S_LEN, HID, HID);
}

// round 8
// speedup vs baseline: 2.2075x; 2.2075x over previous
#include <cuda_runtime.h>
#include <cstdint>

#define S_LEN 4096
#define HID   512
#define NHEAD 8
#define HDIM  64

// Scratch (device globals — allocation-free per harness rules)
__device__ float g_q[S_LEN * HID];
__device__ float g_k[S_LEN * HID];
__device__ float g_v[S_LEN * HID];
__device__ float g_att[S_LEN * HID];

// ---------------------------------------------------------------------------
// Helpers: tf32 convert + m16n8k8 tf32 mma
// ---------------------------------------------------------------------------
__device__ __forceinline__ uint32_t f2tf32(float f) {
    uint32_t u;
    asm("cvt.rna.tf32.f32 %0, %1;" : "=r"(u) : "f"(f));
    return u;
}

__device__ __forceinline__ void mma_tf32(float c[4], const uint32_t a[4],
                                         uint32_t b0, uint32_t b1) {
    asm volatile(
        "mma.sync.aligned.m16n8k8.row.col.f32.tf32.tf32.f32 "
        "{%0,%1,%2,%3}, {%4,%5,%6,%7}, {%8,%9}, {%0,%1,%2,%3};"
        : "+f"(c[0]), "+f"(c[1]), "+f"(c[2]), "+f"(c[3])
        : "r"(a[0]), "r"(a[1]), "r"(a[2]), "r"(a[3]), "r"(b0), "r"(b1));
}

// ---------------------------------------------------------------------------
// C[4096,512] = A[4096,512] * B[512,512]^T  (NT, tf32 mma, fp32 accum)
// CTA tile 128x64, BK=32, 256 threads (8 warps, 4x2), warp tile 32x32.
// smem padded stride 36 (== 4 mod 32): frag LDS bank = 4*(lane/4)+(lane%4)
// -> conflict-free.
// ---------------------------------------------------------------------------
#define GK 512
#define GN 512

__global__ __launch_bounds__(256) void gemm_tf32(const float* __restrict__ A,
                                                 const float* __restrict__ B,
                                                 float* __restrict__ C) {
    __shared__ uint32_t As[128 * 36];
    __shared__ uint32_t Bs[64 * 36];
    const int tid = threadIdx.x;
    const int lane = tid & 31;
    const int warp = tid >> 5;
    const int g = lane >> 2;     // group id (0..7)
    const int c = lane & 3;      // thread-in-group (0..3)
    const int warp_m = warp & 3; // 4 warps in m
    const int warp_n = warp >> 2;
    const int mb = blockIdx.y * 128;
    const int nb = blockIdx.x * 64;

    float acc[2][4][4];
#pragma unroll
    for (int mf = 0; mf < 2; mf++)
#pragma unroll
        for (int nf = 0; nf < 4; nf++)
#pragma unroll
            for (int r = 0; r < 4; r++) acc[mf][nf][r] = 0.f;

    for (int kb = 0; kb < GK; kb += 32) {
        // stage A: 128x32 -> 1024 float4 / 256 thr = 4 each
#pragma unroll
        for (int i = 0; i < 4; i++) {
            int fid = tid + i * 256;
            int r = fid >> 3, c4 = fid & 7;
            float4 v = *reinterpret_cast<const float4*>(&A[(mb + r) * GK + kb + c4 * 4]);
            uint4 u = make_uint4(f2tf32(v.x), f2tf32(v.y), f2tf32(v.z), f2tf32(v.w));
            *reinterpret_cast<uint4*>(&As[r * 36 + c4 * 4]) = u;
        }
        // stage B: 64x32 -> 512 float4 / 256 thr = 2 each
#pragma unroll
        for (int i = 0; i < 2; i++) {
            int fid = tid + i * 256;
            int r = fid >> 3, c4 = fid & 7;
            float4 v = *reinterpret_cast<const float4*>(&B[(nb + r) * GK + kb + c4 * 4]);
            uint4 u = make_uint4(f2tf32(v.x), f2tf32(v.y), f2tf32(v.z), f2tf32(v.w));
            *reinterpret_cast<uint4*>(&Bs[r * 36 + c4 * 4]) = u;
        }
        __syncthreads();

#pragma unroll
        for (int ks = 0; ks < 4; ks++) {
            const int kk = ks * 8;
            uint32_t a[2][4];
#pragma unroll
            for (int mf = 0; mf < 2; mf++) {
                int rowb = warp_m * 32 + mf * 16 + g;
                a[mf][0] = As[rowb * 36 + kk + c];
                a[mf][1] = As[(rowb + 8) * 36 + kk + c];
                a[mf][2] = As[rowb * 36 + kk + c + 4];
                a[mf][3] = As[(rowb + 8) * 36 + kk + c + 4];
            }
            uint32_t b[4][2];
#pragma unroll
            for (int nf = 0; nf < 4; nf++) {
                int colb = warp_n * 32 + nf * 8 + g;
                b[nf][0] = Bs[colb * 36 + kk + c];
                b[nf][1] = Bs[colb * 36 + kk + c + 4];
            }
#pragma unroll
            for (int mf = 0; mf < 2; mf++)
#pragma unroll
                for (int nf = 0; nf < 4; nf++)
                    mma_tf32(acc[mf][nf], a[mf], b[nf][0], b[nf][1]);
        }
        __syncthreads();
    }

    // epilogue: c0,c1 at (row, 2c), (row, 2c+1); c2,c3 at row+8
#pragma unroll
    for (int mf = 0; mf < 2; mf++) {
        int row = mb + warp_m * 32 + mf * 16 + g;
#pragma unroll
        for (int nf = 0; nf < 4; nf++) {
            int col = nb + warp_n * 32 + nf * 8 + 2 * c;
            float2 v0 = make_float2(acc[mf][nf][0], acc[mf][nf][1]);
            *reinterpret_cast<float2*>(&C[row * GN + col]) = v0;
            float2 v1 = make_float2(acc[mf][nf][2], acc[mf][nf][3]);
            *reinterpret_cast<float2*>(&C[(row + 8) * GN + col]) = v1;
        }
    }
}

// ---------------------------------------------------------------------------
// RoPE on Q and K, positions s >= num_registers, rotation index p = s - nreg.
// ---------------------------------------------------------------------------
__global__ void rope_kernel(float* __restrict__ q, float* __restrict__ k,
                            const float* __restrict__ cosb,
                            const float* __restrict__ sinb,
                            const int* __restrict__ nregp) {
    const int nreg = *nregp;
    int idx = blockIdx.x * blockDim.x + threadIdx.x;   // over S*8*32 pairs
    if (idx >= S_LEN * NHEAD * 32) return;
    int j = idx & 31;
    int h = (idx >> 5) & 7;
    int s = idx >> 8;
    if (s < nreg) return;
    int p = s - nreg;
    float c  = cosb[p * HDIM + j];
    float sn = sinb[p * HDIM + j];
    int base = s * HID + h * HDIM + j;
    float q1 = q[base], q2 = q[base + 32];
    q[base]      = q1 * c - q2 * sn;
    q[base + 32] = q2 * c + q1 * sn;
    float k1 = k[base], k2 = k[base + 32];
    k[base]      = k1 * c - k2 * sn;
    k[base + 32] = k2 * c + k1 * sn;
}

// ---------------------------------------------------------------------------
// Flash attention, causal, tf32 mma. 64-query tile, 4 warps x 16 rows.
// Q frags live in registers (loaded once). K stride 68 (==4 mod 32,
// conflict-free for frags indexed row=lane/4, col=lane%4). V stride 72
// (==8 mod 32, conflict-free for PV B-frags indexed row=lane%4, col=lane/4).
// P roundtrips register->smem->a-frag; rows are warp-private -> __syncwarp.
// ---------------------------------------------------------------------------
#define KSTRIDE 68
#define VSTRIDE 72
#define AT_SMEM ((64 * KSTRIDE + 64 * VSTRIDE + 64 * KSTRIDE) * 4)   // 53248 B

__global__ __launch_bounds__(128, 3) void attn_mma(const float* __restrict__ Q,
                                                   const float* __restrict__ Kb,
                                                   const float* __restrict__ Vb,
                                                   float* __restrict__ O) {
    extern __shared__ uint32_t smu[];
    uint32_t* Ks = smu;
    uint32_t* Vs = smu + 64 * KSTRIDE;
    uint32_t* Ps = smu + 64 * KSTRIDE + 64 * VSTRIDE;

    const int tid  = threadIdx.x;
    const int lane = tid & 31;
    const int w    = tid >> 5;
    const int g    = lane >> 2;
    const int c    = lane & 3;
    const int head = blockIdx.x & 7;
    const int qt   = 63 - (blockIdx.x >> 3);   // descending for LPT packing
    const int qbase = qt * 64;
    const int hoff  = head * HDIM;

    // Q fragments in registers, pre-scaled by 1/sqrt(64)
    uint32_t qa[8][4];
    {
        const float scale = 0.125f;
        const float* q0 = Q + (qbase + w * 16 + g) * HID + hoff;
        const float* q1 = q0 + 8 * HID;
#pragma unroll
        for (int ks = 0; ks < 8; ks++) {
            qa[ks][0] = f2tf32(scale * __ldg(q0 + ks * 8 + c));
            qa[ks][1] = f2tf32(scale * __ldg(q1 + ks * 8 + c));
            qa[ks][2] = f2tf32(scale * __ldg(q0 + ks * 8 + c + 4));
            qa[ks][3] = f2tf32(scale * __ldg(q1 + ks * 8 + c + 4));
        }
    }

    float o[8][4];
#pragma unroll
    for (int nf = 0; nf < 8; nf++)
#pragma unroll
        for (int r = 0; r < 4; r++) o[nf][r] = 0.f;
    float m0 = -1e30f, m1 = -1e30f, l0 = 0.f, l1 = 0.f;

    const int prow0 = (w * 16 + g) * KSTRIDE;
    const int prow1 = (w * 16 + g + 8) * KSTRIDE;

    for (int t = 0; t <= qt; t++) {
        const int kb0 = t * 64;
        __syncthreads();   // prior PV reads of Ks/Vs done before overwrite
        // stage K and V tiles (tf32): 1024 float4 each / 128 thr = 8 each
#pragma unroll
        for (int i = 0; i < 8; i++) {
            int fid = tid + i * 128;
            int r = fid >> 4, c4 = fid & 15;
            float4 kv = *reinterpret_cast<const float4*>(&Kb[(kb0 + r) * HID + hoff + c4 * 4]);
            uint4 ku = make_uint4(f2tf32(kv.x), f2tf32(kv.y), f2tf32(kv.z), f2tf32(kv.w));
            *reinterpret_cast<uint4*>(&Ks[r * KSTRIDE + c4 * 4]) = ku;
            float4 vv = *reinterpret_cast<const float4*>(&Vb[(kb0 + r) * HID + hoff + c4 * 4]);
            uint4 vu = make_uint4(f2tf32(vv.x), f2tf32(vv.y), f2tf32(vv.z), f2tf32(vv.w));
            *reinterpret_cast<uint4*>(&Vs[r * VSTRIDE + c4 * 4]) = vu;
        }
        __syncthreads();

        // S = Q K^T
        float s[8][4];
#pragma unroll
        for (int nf = 0; nf < 8; nf++)
#pragma unroll
            for (int r = 0; r < 4; r++) s[nf][r] = 0.f;
#pragma unroll
        for (int ks = 0; ks < 8; ks++) {
            const int kk = ks * 8;
#pragma unroll
            for (int nf = 0; nf < 8; nf++) {
                uint32_t b0 = Ks[(nf * 8 + g) * KSTRIDE + kk + c];
                uint32_t b1 = Ks[(nf * 8 + g) * KSTRIDE + kk + c + 4];
                mma_tf32(s[nf], qa[ks], b0, b1);
            }
        }

        if (t == qt) {   // diagonal tile: mask col > row (local coords)
            int row0 = w * 16 + g, row1 = row0 + 8;
#pragma unroll
            for (int nf = 0; nf < 8; nf++) {
                int col = nf * 8 + 2 * c;
                if (col     > row0) s[nf][0] = -1e30f;
                if (col + 1 > row0) s[nf][1] = -1e30f;
                if (col     > row1) s[nf][2] = -1e30f;
                if (col + 1 > row1) s[nf][3] = -1e30f;
            }
        }

        // online softmax, row r0 (regs [0],[1]) and row r1 (regs [2],[3])
        float mx0 = -1e30f, mx1 = -1e30f;
#pragma unroll
        for (int nf = 0; nf < 8; nf++) {
            mx0 = fmaxf(mx0, fmaxf(s[nf][0], s[nf][1]));
            mx1 = fmaxf(mx1, fmaxf(s[nf][2], s[nf][3]));
        }
        mx0 = fmaxf(mx0, __shfl_xor_sync(0xffffffffu, mx0, 1));
        mx0 = fmaxf(mx0, __shfl_xor_sync(0xffffffffu, mx0, 2));
        mx1 = fmaxf(mx1, __shfl_xor_sync(0xffffffffu, mx1, 1));
        mx1 = fmaxf(mx1, __shfl_xor_sync(0xffffffffu, mx1, 2));
        float mn0 = fmaxf(m0, mx0), mn1 = fmaxf(m1, mx1);
        float al0 = __expf(m0 - mn0), al1 = __expf(m1 - mn1);
        float sum0 = 0.f, sum1 = 0.f;
#pragma unroll
        for (int nf = 0; nf < 8; nf++) {
            s[nf][0] = __expf(s[nf][0] - mn0);
            s[nf][1] = __expf(s[nf][1] - mn0);
            sum0 += s[nf][0] + s[nf][1];
            s[nf][2] = __expf(s[nf][2] - mn1);
            s[nf][3] = __expf(s[nf][3] - mn1);
            sum1 += s[nf][2] + s[nf][3];
        }
        sum0 += __shfl_xor_sync(0xffffffffu, sum0, 1);
        sum0 += __shfl_xor_sync(0xffffffffu, sum0, 2);
        sum1 += __shfl_xor_sync(0xffffffffu, sum1, 1);
        sum1 += __shfl_xor_sync(0xffffffffu, sum1, 2);
        l0 = l0 * al0 + sum0;  m0 = mn0;
        l1 = l1 * al1 + sum1;  m1 = mn1;
#pragma unroll
        for (int nf = 0; nf < 8; nf++) {
            o[nf][0] *= al0;  o[nf][1] *= al0;
            o[nf][2] *= al1;  o[nf][3] *= al1;
        }

        // stash P as tf32 (rows are warp-private)
#pragma unroll
        for (int nf = 0; nf < 8; nf++) {
            uint2 pa = make_uint2(f2tf32(s[nf][0]), f2tf32(s[nf][1]));
            *reinterpret_cast<uint2*>(&Ps[prow0 + nf * 8 + 2 * c]) = pa;
            uint2 pb = make_uint2(f2tf32(s[nf][2]), f2tf32(s[nf][3]));
            *reinterpret_cast<uint2*>(&Ps[prow1 + nf * 8 + 2 * c]) = pb;
        }
        __syncwarp();

        // O += P V
#pragma unroll
        for (int ks = 0; ks < 8; ks++) {
            const int kk = ks * 8;
            uint32_t a[4];
            a[0] = Ps[prow0 + kk + c];
            a[1] = Ps[prow1 + kk + c];
            a[2] = Ps[prow0 + kk + c + 4];
            a[3] = Ps[prow1 + kk + c + 4];
#pragma unroll
            for (int nf = 0; nf < 8; nf++) {
                uint32_t b0 = Vs[(kk + c) * VSTRIDE + nf * 8 + g];
                uint32_t b1 = Vs[(kk + c + 4) * VSTRIDE + nf * 8 + g];
                mma_tf32(o[nf], a, b0, b1);
            }
        }
    }

    // epilogue
    float inv0 = 1.0f / l0, inv1 = 1.0f / l1;
    int row = qbase + w * 16 + g;
#pragma unroll
    for (int nf = 0; nf < 8; nf++) {
        int col = hoff + nf * 8 + 2 * c;
        float2 v0 = make_float2(o[nf][0] * inv0, o[nf][1] * inv0);
        *reinterpret_cast<float2*>(&O[row * HID + col]) = v0;
        float2 v1 = make_float2(o[nf][2] * inv1, o[nf][3] * inv1);
        *reinterpret_cast<float2*>(&O[(row + 8) * HID + col]) = v1;
    }
}

// ---------------------------------------------------------------------------
// Host launcher (graph-capturable: kernel launches only)
// Inputs: hidden, Wq, Wk, Wv, Wo, cos, sin, num_registers
// ---------------------------------------------------------------------------
extern "C" void kernel_launch(void* const* d_in, const int* in_sizes, int n_in,
                              void* d_out, int out_size) {
    const float* hs   = (const float*)d_in[0];
    const float* Wq   = (const float*)d_in[1];
    const float* Wk   = (const float*)d_in[2];
    const float* Wv   = (const float*)d_in[3];
    const float* Wo   = (const float*)d_in[4];
    const float* cosb = (const float*)d_in[5];
    const float* sinb = (const float*)d_in[6];
    const int*   nreg = (const int*)d_in[7];
    float* out = (float*)d_out;

    float *qp, *kp, *vp, *ap;
    cudaGetSymbolAddress((void**)&qp, g_q);
    cudaGetSymbolAddress((void**)&kp, g_k);
    cudaGetSymbolAddress((void**)&vp, g_v);
    cudaGetSymbolAddress((void**)&ap, g_att);

    dim3 ggrid(GN / 64, S_LEN / 128);   // (8, 32)
    gemm_tf32<<<ggrid, 256>>>(hs, Wq, qp);
    gemm_tf32<<<ggrid, 256>>>(hs, Wk, kp);
    gemm_tf32<<<ggrid, 256>>>(hs, Wv, vp);

    rope_kernel<<<(S_LEN * NHEAD * 32 + 255) / 256, 256>>>(qp, kp, cosb, sinb, nreg);

    cudaFuncSetAttribute(attn_mma, cudaFuncAttributeMaxDynamicSharedMemorySize, AT_SMEM);
    attn_mma<<<512, 128, AT_SMEM>>>(qp, kp, vp, ap);

    gemm_tf32<<<ggrid, 256>>>(ap, Wo, out);
}

// round 9
// speedup vs baseline: 3.5222x; 1.5956x over previous
#include <cuda_runtime.h>
#include <cstdint>

#define S_LEN 4096
#define HID   512
#define NHEAD 8
#define HDIM  64
#define GK    512
#define GN    512

// Scratch (device globals — allocation-free per harness rules)
__device__ float g_q[S_LEN * HID];
__device__ float g_k[S_LEN * HID];
__device__ float g_v[S_LEN * HID];
__device__ float g_att[S_LEN * HID];

// ---------------------------------------------------------------------------
// Helpers
// ---------------------------------------------------------------------------
__device__ __forceinline__ uint32_t f2tf32(float f) {
    uint32_t u;
    asm("cvt.rna.tf32.f32 %0, %1;" : "=r"(u) : "f"(f));
    return u;
}

__device__ __forceinline__ void mma_tf32(float c[4], const uint32_t a[4],
                                         uint32_t b0, uint32_t b1) {
    asm volatile(
        "mma.sync.aligned.m16n8k8.row.col.f32.tf32.tf32.f32 "
        "{%0,%1,%2,%3}, {%4,%5,%6,%7}, {%8,%9}, {%0,%1,%2,%3};"
        : "+f"(c[0]), "+f"(c[1]), "+f"(c[2]), "+f"(c[3])
        : "r"(a[0]), "r"(a[1]), "r"(a[2]), "r"(a[3]), "r"(b0), "r"(b1));
}

__device__ __forceinline__ uint32_t smem_u32(const void* p) {
    return (uint32_t)__cvta_generic_to_shared(p);
}

__device__ __forceinline__ void cp16(uint32_t dst, const float* src) {
    asm volatile("cp.async.cg.shared.global [%0], [%1], 16;" :: "r"(dst), "l"(src));
}
#define CP_COMMIT() asm volatile("cp.async.commit_group;")
#define CP_WAIT0()  asm volatile("cp.async.wait_group 0;")

// ---------------------------------------------------------------------------
// C[4096,512] = A[4096,512] * B[512,512]^T  (NT, tf32 mma, fp32 accum)
// CTA 128x64, BK=32, 256 thr (8 warps 4x2), warp tile 32x32.
// cp.async double-buffered; raw fp32 in smem (stride 36 == 4 mod 32,
// frag LDS provably conflict-free); cvt.rna at frag load.
// gridDim.z selects (B,C) so QKV is a single launch.
// ---------------------------------------------------------------------------
#define GA_BUF (128 * 36)
#define GB_BUF (64 * 36)
#define GEMM_SMEM ((2 * GA_BUF + 2 * GB_BUF) * 4)   // 55296 B

__global__ __launch_bounds__(256) void gemm_tf32(const float* __restrict__ A,
                                                 const float* __restrict__ B0,
                                                 const float* __restrict__ B1,
                                                 const float* __restrict__ B2,
                                                 float* __restrict__ C0,
                                                 float* __restrict__ C1,
                                                 float* __restrict__ C2) {
    extern __shared__ float gsm[];
    float* Asm = gsm;                 // [2][128][36]
    float* Bsm = gsm + 2 * GA_BUF;    // [2][64][36]
    const uint32_t sA = smem_u32(Asm);
    const uint32_t sB = smem_u32(Bsm);

    const float* B = (blockIdx.z == 0) ? B0 : (blockIdx.z == 1) ? B1 : B2;
    float*       C = (blockIdx.z == 0) ? C0 : (blockIdx.z == 1) ? C1 : C2;

    const int tid = threadIdx.x;
    const int lane = tid & 31;
    const int warp = tid >> 5;
    const int g = lane >> 2;
    const int c = lane & 3;
    const int warp_m = warp & 3;
    const int warp_n = warp >> 2;
    const int mb = blockIdx.y * 128;
    const int nb = blockIdx.x * 64;

    // stage lambda: tile at kb into buffer buf
    auto stage = [&](int kb, int buf) {
        const int ab = buf * GA_BUF, bb = buf * GB_BUF;
#pragma unroll
        for (int i = 0; i < 4; i++) {
            int fid = tid + i * 256;
            int r = fid >> 3, c4 = fid & 7;
            cp16(sA + (ab + r * 36 + c4 * 4) * 4, A + (mb + r) * GK + kb + c4 * 4);
        }
#pragma unroll
        for (int i = 0; i < 2; i++) {
            int fid = tid + i * 256;
            int r = fid >> 3, c4 = fid & 7;
            cp16(sB + (bb + r * 36 + c4 * 4) * 4, B + (nb + r) * GK + kb + c4 * 4);
        }
        CP_COMMIT();
    };

    float acc[2][4][4];
#pragma unroll
    for (int mf = 0; mf < 2; mf++)
#pragma unroll
        for (int nf = 0; nf < 4; nf++)
#pragma unroll
            for (int r = 0; r < 4; r++) acc[mf][nf][r] = 0.f;

    stage(0, 0);

    for (int ib = 0; ib < GK / 32; ib++) {
        CP_WAIT0();
        __syncthreads();   // tile ib visible; all warps done with buf[(ib+1)&1]
        if (ib + 1 < GK / 32) stage((ib + 1) * 32, (ib + 1) & 1);

        const float* Ab = Asm + (ib & 1) * GA_BUF;
        const float* Bb = Bsm + (ib & 1) * GB_BUF;
#pragma unroll
        for (int ks = 0; ks < 4; ks++) {
            const int kk = ks * 8;
            uint32_t a[2][4];
#pragma unroll
            for (int mf = 0; mf < 2; mf++) {
                int rowb = warp_m * 32 + mf * 16 + g;
                a[mf][0] = f2tf32(Ab[rowb * 36 + kk + c]);
                a[mf][1] = f2tf32(Ab[(rowb + 8) * 36 + kk + c]);
                a[mf][2] = f2tf32(Ab[rowb * 36 + kk + c + 4]);
                a[mf][3] = f2tf32(Ab[(rowb + 8) * 36 + kk + c + 4]);
            }
            uint32_t b[4][2];
#pragma unroll
            for (int nf = 0; nf < 4; nf++) {
                int colb = warp_n * 32 + nf * 8 + g;
                b[nf][0] = f2tf32(Bb[colb * 36 + kk + c]);
                b[nf][1] = f2tf32(Bb[colb * 36 + kk + c + 4]);
            }
#pragma unroll
            for (int mf = 0; mf < 2; mf++)
#pragma unroll
                for (int nf = 0; nf < 4; nf++)
                    mma_tf32(acc[mf][nf], a[mf], b[nf][0], b[nf][1]);
        }
    }

#pragma unroll
    for (int mf = 0; mf < 2; mf++) {
        int row = mb + warp_m * 32 + mf * 16 + g;
#pragma unroll
        for (int nf = 0; nf < 4; nf++) {
            int col = nb + warp_n * 32 + nf * 8 + 2 * c;
            *reinterpret_cast<float2*>(&C[row * GN + col]) =
                make_float2(acc[mf][nf][0], acc[mf][nf][1]);
            *reinterpret_cast<float2*>(&C[(row + 8) * GN + col]) =
                make_float2(acc[mf][nf][2], acc[mf][nf][3]);
        }
    }
}

// ---------------------------------------------------------------------------
// RoPE on Q and K, positions s >= num_registers.
// ---------------------------------------------------------------------------
__global__ void rope_kernel(float* __restrict__ q, float* __restrict__ k,
                            const float* __restrict__ cosb,
                            const float* __restrict__ sinb,
                            const int* __restrict__ nregp) {
    const int nreg = *nregp;
    int idx = blockIdx.x * blockDim.x + threadIdx.x;
    if (idx >= S_LEN * NHEAD * 32) return;
    int j = idx & 31;
    int h = (idx >> 5) & 7;
    int s = idx >> 8;
    if (s < nreg) return;
    int p = s - nreg;
    float c  = cosb[p * HDIM + j];
    float sn = sinb[p * HDIM + j];
    int base = s * HID + h * HDIM + j;
    float q1 = q[base], q2 = q[base + 32];
    q[base]      = q1 * c - q2 * sn;
    q[base + 32] = q2 * c + q1 * sn;
    float k1 = k[base], k2 = k[base + 32];
    k[base]      = k1 * c - k2 * sn;
    k[base + 32] = k2 * c + k1 * sn;
}

// ---------------------------------------------------------------------------
// Flash attention, causal, tf32 mma, cp.async double-buffered KV.
// 64-query tile, 128 thr (4 warps x 16 rows). Q frags in registers.
// K raw fp32, stride 68 (==4 mod 32: S b-frag LDS conflict-free).
// V raw fp32, stride 72 (==8 mod 32: PV b-frag LDS conflict-free).
// P (tf32) aliases the CURRENT K buffer after the S phase (K dead by then;
// guarded by one __syncthreads). 3 CTAs/SM (71.7 KB smem each).
// ---------------------------------------------------------------------------
#define KSTRIDE 68
#define VSTRIDE 72
#define KBUF (64 * KSTRIDE)          // 4352 words
#define VBUF (64 * VSTRIDE)          // 4608 words
#define AT_SMEM ((2 * KBUF + 2 * VBUF) * 4)   // 71680 B

__global__ __launch_bounds__(128, 3) void attn_mma(const float* __restrict__ Q,
                                                   const float* __restrict__ Kg,
                                                   const float* __restrict__ Vg,
                                                   float* __restrict__ O) {
    extern __shared__ float sm[];
    float* Ksm = sm;                  // [2][64][68]
    float* Vsm = sm + 2 * KBUF;       // [2][64][72]
    const uint32_t sK = smem_u32(Ksm);
    const uint32_t sV = smem_u32(Vsm);

    const int tid  = threadIdx.x;
    const int lane = tid & 31;
    const int w    = tid >> 5;
    const int g    = lane >> 2;
    const int c    = lane & 3;
    const int head = blockIdx.x & 7;
    const int qt   = 63 - (blockIdx.x >> 3);   // descending for LPT packing
    const int qbase = qt * 64;
    const int hoff  = head * HDIM;

    auto stage = [&](int t, int buf) {
        const int kb0 = t * 64;
        const int kb = buf * KBUF, vb = buf * VBUF;
#pragma unroll
        for (int i = 0; i < 8; i++) {
            int fid = tid + i * 128;
            int r = fid >> 4, c4 = fid & 15;
            cp16(sK + (kb + r * KSTRIDE + c4 * 4) * 4,
                 Kg + (kb0 + r) * HID + hoff + c4 * 4);
            cp16(sV + (vb + r * VSTRIDE + c4 * 4) * 4,
                 Vg + (kb0 + r) * HID + hoff + c4 * 4);
        }
        CP_COMMIT();
    };

    stage(0, 0);

    // Q fragments in registers, pre-scaled by 1/sqrt(64)
    uint32_t qa[8][4];
    {
        const float scale = 0.125f;
        const float* q0 = Q + (qbase + w * 16 + g) * HID + hoff;
        const float* q1 = q0 + 8 * HID;
#pragma unroll
        for (int ks = 0; ks < 8; ks++) {
            qa[ks][0] = f2tf32(scale * __ldg(q0 + ks * 8 + c));
            qa[ks][1] = f2tf32(scale * __ldg(q1 + ks * 8 + c));
            qa[ks][2] = f2tf32(scale * __ldg(q0 + ks * 8 + c + 4));
            qa[ks][3] = f2tf32(scale * __ldg(q1 + ks * 8 + c + 4));
        }
    }

    float o[8][4];
#pragma unroll
    for (int nf = 0; nf < 8; nf++)
#pragma unroll
        for (int r = 0; r < 4; r++) o[nf][r] = 0.f;
    float m0 = -1e30f, m1 = -1e30f, l0 = 0.f, l1 = 0.f;

    const int prow0 = (w * 16 + g) * KSTRIDE;
    const int prow1 = (w * 16 + g + 8) * KSTRIDE;

    for (int t = 0; t <= qt; t++) {
        CP_WAIT0();
        __syncthreads();   // tile t visible; all warps done with prior P/V reads
        if (t < qt) stage(t + 1, (t + 1) & 1);

        const float* Kf = Ksm + (t & 1) * KBUF;
        const float* Vf = Vsm + (t & 1) * VBUF;

        // S = Q K^T
        float s[8][4];
#pragma unroll
        for (int nf = 0; nf < 8; nf++)
#pragma unroll
            for (int r = 0; r < 4; r++) s[nf][r] = 0.f;
#pragma unroll
        for (int ks = 0; ks < 8; ks++) {
            const int kk = ks * 8;
#pragma unroll
            for (int nf = 0; nf < 8; nf++) {
                uint32_t b0 = f2tf32(Kf[(nf * 8 + g) * KSTRIDE + kk + c]);
                uint32_t b1 = f2tf32(Kf[(nf * 8 + g) * KSTRIDE + kk + c + 4]);
                mma_tf32(s[nf], qa[ks], b0, b1);
            }
        }

        if (t == qt) {   // diagonal tile mask (local coords)
            int row0 = w * 16 + g, row1 = row0 + 8;
#pragma unroll
            for (int nf = 0; nf < 8; nf++) {
                int col = nf * 8 + 2 * c;
                if (col     > row0) s[nf][0] = -1e30f;
                if (col + 1 > row0) s[nf][1] = -1e30f;
                if (col     > row1) s[nf][2] = -1e30f;
                if (col + 1 > row1) s[nf][3] = -1e30f;
            }
        }

        // online softmax (rows r0: regs 0,1 / r1: regs 2,3)
        float mx0 = -1e30f, mx1 = -1e30f;
#pragma unroll
        for (int nf = 0; nf < 8; nf++) {
            mx0 = fmaxf(mx0, fmaxf(s[nf][0], s[nf][1]));
            mx1 = fmaxf(mx1, fmaxf(s[nf][2], s[nf][3]));
        }
        mx0 = fmaxf(mx0, __shfl_xor_sync(0xffffffffu, mx0, 1));
        mx0 = fmaxf(mx0, __shfl_xor_sync(0xffffffffu, mx0, 2));
        mx1 = fmaxf(mx1, __shfl_xor_sync(0xffffffffu, mx1, 1));
        mx1 = fmaxf(mx1, __shfl_xor_sync(0xffffffffu, mx1, 2));
        float mn0 = fmaxf(m0, mx0), mn1 = fmaxf(m1, mx1);
        float al0 = __expf(m0 - mn0), al1 = __expf(m1 - mn1);
        float sum0 = 0.f, sum1 = 0.f;
#pragma unroll
        for (int nf = 0; nf < 8; nf++) {
            s[nf][0] = __expf(s[nf][0] - mn0);
            s[nf][1] = __expf(s[nf][1] - mn0);
            sum0 += s[nf][0] + s[nf][1];
            s[nf][2] = __expf(s[nf][2] - mn1);
            s[nf][3] = __expf(s[nf][3] - mn1);
            sum1 += s[nf][2] + s[nf][3];
        }
        sum0 += __shfl_xor_sync(0xffffffffu, sum0, 1);
        sum0 += __shfl_xor_sync(0xffffffffu, sum0, 2);
        sum1 += __shfl_xor_sync(0xffffffffu, sum1, 1);
        sum1 += __shfl_xor_sync(0xffffffffu, sum1, 2);
        l0 = l0 * al0 + sum0;  m0 = mn0;
        l1 = l1 * al1 + sum1;  m1 = mn1;
#pragma unroll
        for (int nf = 0; nf < 8; nf++) {
            o[nf][0] *= al0;  o[nf][1] *= al0;
            o[nf][2] *= al1;  o[nf][3] *= al1;
        }

        __syncthreads();   // all warps done reading Kf -> safe to alias with P
        uint32_t* Pp = reinterpret_cast<uint32_t*>(const_cast<float*>(Kf));
#pragma unroll
        for (int nf = 0; nf < 8; nf++) {
            *reinterpret_cast<uint2*>(&Pp[prow0 + nf * 8 + 2 * c]) =
                make_uint2(f2tf32(s[nf][0]), f2tf32(s[nf][1]));
            *reinterpret_cast<uint2*>(&Pp[prow1 + nf * 8 + 2 * c]) =
                make_uint2(f2tf32(s[nf][2]), f2tf32(s[nf][3]));
        }
        __syncwarp();      // P rows are warp-private

        // O += P V
#pragma unroll
        for (int ks = 0; ks < 8; ks++) {
            const int kk = ks * 8;
            uint32_t a[4];
            a[0] = Pp[prow0 + kk + c];
            a[1] = Pp[prow1 + kk + c];
            a[2] = Pp[prow0 + kk + c + 4];
            a[3] = Pp[prow1 + kk + c + 4];
#pragma unroll
            for (int nf = 0; nf < 8; nf++) {
                uint32_t b0 = f2tf32(Vf[(kk + c) * VSTRIDE + nf * 8 + g]);
                uint32_t b1 = f2tf32(Vf[(kk + c + 4) * VSTRIDE + nf * 8 + g]);
                mma_tf32(o[nf], a, b0, b1);
            }
        }
    }

    // epilogue
    float inv0 = 1.0f / l0, inv1 = 1.0f / l1;
    int row = qbase + w * 16 + g;
#pragma unroll
    for (int nf = 0; nf < 8; nf++) {
        int col = hoff + nf * 8 + 2 * c;
        *reinterpret_cast<float2*>(&O[row * HID + col]) =
            make_float2(o[nf][0] * inv0, o[nf][1] * inv0);
        *reinterpret_cast<float2*>(&O[(row + 8) * HID + col]) =
            make_float2(o[nf][2] * inv1, o[nf][3] * inv1);
    }
}

// ---------------------------------------------------------------------------
// Host launcher (graph-capturable: kernel launches only)
// Inputs: hidden, Wq, Wk, Wv, Wo, cos, sin, num_registers
// ---------------------------------------------------------------------------
extern "C" void kernel_launch(void* const* d_in, const int* in_sizes, int n_in,
                              void* d_out, int out_size) {
    const float* hs   = (const float*)d_in[0];
    const float* Wq   = (const float*)d_in[1];
    const float* Wk   = (const float*)d_in[2];
    const float* Wv   = (const float*)d_in[3];
    const float* Wo   = (const float*)d_in[4];
    const float* cosb = (const float*)d_in[5];
    const float* sinb = (const float*)d_in[6];
    const int*   nreg = (const int*)d_in[7];
    float* out = (float*)d_out;

    float *qp, *kp, *vp, *ap;
    cudaGetSymbolAddress((void**)&qp, g_q);
    cudaGetSymbolAddress((void**)&kp, g_k);
    cudaGetSymbolAddress((void**)&vp, g_v);
    cudaGetSymbolAddress((void**)&ap, g_att);

    cudaFuncSetAttribute(gemm_tf32, cudaFuncAttributeMaxDynamicSharedMemorySize, GEMM_SMEM);
    cudaFuncSetAttribute(attn_mma,  cudaFuncAttributeMaxDynamicSharedMemorySize, AT_SMEM);

    // fused QKV projections (gridDim.z selects weight/output)
    dim3 qkv_grid(GN / 64, S_LEN / 128, 3);
    gemm_tf32<<<qkv_grid, 256, GEMM_SMEM>>>(hs, Wq, Wk, Wv, qp, kp, vp);

    rope_kernel<<<(S_LEN * NHEAD * 32 + 255) / 256, 256>>>(qp, kp, cosb, sinb, nreg);

    attn_mma<<<512, 128, AT_SMEM>>>(qp, kp, vp, ap);

    dim3 o_grid(GN / 64, S_LEN / 128, 1);
    gemm_tf32<<<o_grid, 256, GEMM_SMEM>>>(ap, Wo, Wo, Wo, out, out, out);
}